// round 7
// baseline (speedup 1.0000x reference)
#include <cuda_runtime.h>
#include <cuda_bf16.h>
#include <cstdint>

// ============================================================================
// BiBoSparseMoeBlock: top-2-of-8 MoE SwiGLU, fp32 in/out.
// Round 7: round-6 design (wide N=128 tiles, 3-stage wait_group(1) pipeline,
// 512-thread CTA) with the gate+up epilogue column-coverage bug fixed
// (seg = (tid&3)*16, 8 pairs -> full 64 inter cols per CTA).
// ============================================================================

#define HID   2048
#define INTER 1024
#define NEXP  8
#define MAXT  4096
#define MAXSLOTS (2 * MAXT)

typedef unsigned int u32;

// ---- device scratch ---------------------------------------------------------
__device__ int   g_cnt[NEXP];
__device__ int   g_off[NEXP];
__device__ int   g_fill[NEXP];
__device__ int   g_perm[MAXSLOTS];
__device__ float g_w[MAXSLOTS];
__device__ int   g_tidx[MAXT * 2];
__device__ float g_tw[MAXT * 2];
__device__ int   g_slot_of[MAXT * 2];

__device__ __nv_bfloat16 g_Xh[(size_t)MAXT * HID];
__device__ __nv_bfloat16 g_Xl[(size_t)MAXT * HID];
__device__ __nv_bfloat16 g_Wgh[(size_t)NEXP * INTER * HID];
__device__ __nv_bfloat16 g_Wgl[(size_t)NEXP * INTER * HID];
__device__ __nv_bfloat16 g_Wuh[(size_t)NEXP * INTER * HID];
__device__ __nv_bfloat16 g_Wul[(size_t)NEXP * INTER * HID];
__device__ __nv_bfloat16 g_Wdh[(size_t)NEXP * HID * INTER];
__device__ __nv_bfloat16 g_Wdl[(size_t)NEXP * HID * INTER];
__device__ __nv_bfloat16 g_Hh[(size_t)MAXSLOTS * INTER];
__device__ __nv_bfloat16 g_Hl[(size_t)MAXSLOTS * INTER];
__device__ float g_y[(size_t)MAXSLOTS * HID];

// ---- PTX helpers (baseline sm_80-era only) -------------------------------------
__device__ __forceinline__ u32 smem_u32(const void* p) {
    u32 a;
    asm("{ .reg .u64 t; cvta.to.shared.u64 t, %1; cvt.u32.u64 %0, t; }" : "=r"(a) : "l"(p));
    return a;
}
__device__ __forceinline__ void cpa16(u32 dst, const void* src) {
    asm volatile("cp.async.cg.shared.global [%0], [%1], 16;" :: "r"(dst), "l"(src));
}
#define CPA_COMMIT() asm volatile("cp.async.commit_group;" ::: "memory")
#define CPA_WAIT1()  asm volatile("cp.async.wait_group 1;" ::: "memory")
#define CPA_WAIT0()  asm volatile("cp.async.wait_group 0;" ::: "memory")

__device__ __forceinline__ void ldsm4(u32* r, u32 addr) {
    asm volatile("ldmatrix.sync.aligned.m8n8.x4.shared.b16 {%0,%1,%2,%3}, [%4];"
                 : "=r"(r[0]), "=r"(r[1]), "=r"(r[2]), "=r"(r[3]) : "r"(addr));
}
__device__ __forceinline__ void mma16816(float* c, const u32* a, u32 b0, u32 b1) {
    asm volatile(
        "mma.sync.aligned.m16n8k16.row.col.f32.bf16.bf16.f32 "
        "{%0,%1,%2,%3}, {%4,%5,%6,%7}, {%8,%9}, {%0,%1,%2,%3};"
        : "+f"(c[0]), "+f"(c[1]), "+f"(c[2]), "+f"(c[3])
        : "r"(a[0]), "r"(a[1]), "r"(a[2]), "r"(a[3]), "r"(b0), "r"(b1));
}

// ---- smem geometry: BK=32 bf16 rows (64B data), pitch 80B ----------------------
#define PITCH 80
#define OFF_AH 0
#define OFF_AL 10240          // 128 rows * 80
#define OFF_BH 20480          // B: 128 rows
#define OFF_BL 30720
#define STAGE_BYTES 40960
#define NSTAGE 3
#define SMEM_DYN (NSTAGE * STAGE_BYTES)   // 122880

// ---- small kernels --------------------------------------------------------------
__global__ void zero_counters_kernel() {
    int i = threadIdx.x;
    if (i < NEXP) { g_cnt[i] = 0; g_fill[i] = 0; }
}

__global__ void router_kernel(const float* __restrict__ x,
                              const float* __restrict__ Wr,
                              float* __restrict__ logits_out, int write_logits) {
    const int t = blockIdx.x;
    const int warp = threadIdx.x >> 5;
    const int lane = threadIdx.x & 31;
    __shared__ float slog[NEXP];
    const float* xr = x + (size_t)t * HID;
    const float* wr = Wr + (size_t)warp * HID;
    float s = 0.0f;
    #pragma unroll 4
    for (int i = lane; i < HID; i += 32) s += xr[i] * wr[i];
    #pragma unroll
    for (int o = 16; o > 0; o >>= 1) s += __shfl_xor_sync(0xffffffffu, s, o);
    if (lane == 0) slog[warp] = s;
    __syncthreads();
    if (write_logits && threadIdx.x < NEXP)
        logits_out[t * NEXP + threadIdx.x] = slog[threadIdx.x];
    if (threadIdx.x == 0) {
        float v0 = -1e30f; int i0 = 0;
        #pragma unroll
        for (int i = 0; i < NEXP; i++) if (slog[i] > v0) { v0 = slog[i]; i0 = i; }
        float v1 = -1e30f; int i1 = 0;
        #pragma unroll
        for (int i = 0; i < NEXP; i++)
            if (i != i0 && slog[i] > v1) { v1 = slog[i]; i1 = i; }
        float ex = expf(v1 - v0);
        float inv = 1.0f / (1.0f + ex);
        g_tidx[2 * t] = i0; g_tidx[2 * t + 1] = i1;
        g_tw[2 * t] = inv;  g_tw[2 * t + 1] = ex * inv;
        atomicAdd(&g_cnt[i0], 1);
        atomicAdd(&g_cnt[i1], 1);
    }
}

__global__ void offsets_kernel() {
    if (threadIdx.x == 0) {
        int o = 0;
        #pragma unroll
        for (int e = 0; e < NEXP; e++) { g_off[e] = o; o += g_cnt[e]; }
    }
}

__global__ void scatter_kernel(int T) {
    int t = blockIdx.x * blockDim.x + threadIdx.x;
    if (t >= T) return;
    #pragma unroll
    for (int j = 0; j < 2; j++) {
        int e = g_tidx[2 * t + j];
        int p = atomicAdd(&g_fill[e], 1);
        int slot = g_off[e] + p;
        g_perm[slot] = t;
        g_w[slot] = g_tw[2 * t + j];
        g_slot_of[2 * t + j] = slot;
    }
}

// fused fp32 -> (bf16 hi, bf16 lo) split over x, Wg, Wu, Wd
__device__ __forceinline__ void split4_store(const float4 v, u32* dh, u32* dl, int i) {
    __nv_bfloat162 A = __floats2bfloat162_rn(v.x, v.y);
    __nv_bfloat162 B = __floats2bfloat162_rn(v.z, v.w);
    __nv_bfloat162 Ar = __floats2bfloat162_rn(v.x - __low2float(A), v.y - __high2float(A));
    __nv_bfloat162 Br = __floats2bfloat162_rn(v.z - __low2float(B), v.w - __high2float(B));
    ((uint2*)dh)[i] = make_uint2(*(u32*)&A, *(u32*)&B);
    ((uint2*)dl)[i] = make_uint2(*(u32*)&Ar, *(u32*)&Br);
}

__global__ void split_all_kernel(const float* __restrict__ x,
                                 const float* __restrict__ Wg,
                                 const float* __restrict__ Wu,
                                 const float* __restrict__ Wd, int nx, int nw) {
    int i = blockIdx.x * blockDim.x + threadIdx.x;
    if (i < nx) {
        split4_store(((const float4*)x)[i], (u32*)g_Xh, (u32*)g_Xl, i);
    } else if (i < nx + nw) {
        int j = i - nx;
        split4_store(((const float4*)Wg)[j], (u32*)g_Wgh, (u32*)g_Wgl, j);
    } else if (i < nx + 2 * nw) {
        int j = i - nx - nw;
        split4_store(((const float4*)Wu)[j], (u32*)g_Wuh, (u32*)g_Wul, j);
    } else if (i < nx + 3 * nw) {
        int j = i - nx - 2 * nw;
        split4_store(((const float4*)Wd)[j], (u32*)g_Wdh, (u32*)g_Wdl, j);
    }
}

// ---- GEMM 1: gate+up. CTA: 128 slots x (64 gate + 64 up), 512 thr, K=2048 -------
__global__ __launch_bounds__(512, 1) void gateup_mma_kernel() {
    const int e   = blockIdx.z;
    const int cnt = g_cnt[e];
    const int m0  = blockIdx.y * 128;
    if (m0 >= cnt) return;
    const int rows = min(cnt - m0, 128);
    const int base = g_off[e] + m0;
    const int n0   = blockIdx.x * 64;

    extern __shared__ char dsm[];
    const u32 sm0 = smem_u32(dsm);

    const int tid  = threadIdx.x;
    const int lane = tid & 31;
    const int wid  = tid >> 5;          // 0..15
    const int wm   = wid >> 3;          // 0..1 -> 64-row half
    const int wn   = wid & 7;           // 0..7 -> 16 cols (gate if <4 else up)

    // ---- loader: thread owns ONE 64B row (4 x cp.async 16B) ----
    const int u = tid & 127;            // row within matrix
    const int v = tid >> 7;             // 0:Ah 1:Al 2:Bh 3:Bl
    const __nv_bfloat16* p0;
    if (v < 2) {
        const int ra = min(u, rows - 1);
        p0 = (v ? g_Xl : g_Xh) + (size_t)g_perm[base + ra] * HID;
    } else {
        // B rows: 0..63 = Wg[n0+u], 64..127 = Wu[n0+u-64]
        if (u < 64) p0 = (v == 2 ? g_Wgh : g_Wgl) + ((size_t)e * INTER + n0 + u) * HID;
        else        p0 = (v == 2 ? g_Wuh : g_Wul) + ((size_t)e * INTER + n0 + (u - 64)) * HID;
    }
    const u32 offv = (v == 0) ? OFF_AH : (v == 1) ? OFF_AL : (v == 2) ? OFF_BH : OFF_BL;
    const u32 d0 = offv + (u32)u * PITCH;

    // ---- ldmatrix bases ----
    const u32 a_off = (u32)((wm * 64 + (lane & 7) + ((lane >> 3) & 1) * 8) * PITCH
                    + (lane >> 4) * 16);
    const u32 b_off = (u32)((wn * 16 + (lane & 7) + (lane >> 4) * 8) * PITCH
                    + ((lane >> 3) & 1) * 16);

    float acc[4][2][4];
    #pragma unroll
    for (int i = 0; i < 4; i++)
        #pragma unroll
        for (int j = 0; j < 2; j++)
            #pragma unroll
            for (int k = 0; k < 4; k++) acc[i][j][k] = 0.0f;

    const int KT = HID / 32;            // 64

    #pragma unroll
    for (int p = 0; p < NSTAGE - 1; p++) {
        const u32 sb = sm0 + (u32)p * STAGE_BYTES;
        const size_t ko = (size_t)p * 32;
        #pragma unroll
        for (int c = 0; c < 4; c++) cpa16(sb + d0 + c * 16, p0 + ko + c * 8);
        CPA_COMMIT();
    }

    #pragma unroll 1
    for (int kt = 0; kt < KT; kt++) {
        if (kt == KT - 1) CPA_WAIT0(); else CPA_WAIT1();
        __syncthreads();
        if (kt + NSTAGE - 1 < KT) {
            const u32 sb = sm0 + (u32)((kt + NSTAGE - 1) % NSTAGE) * STAGE_BYTES;
            const size_t ko = (size_t)(kt + NSTAGE - 1) * 32;
            #pragma unroll
            for (int c = 0; c < 4; c++) cpa16(sb + d0 + c * 16, p0 + ko + c * 8);
            CPA_COMMIT();
        }
        const u32 sb = sm0 + (u32)(kt % NSTAGE) * STAGE_BYTES;
        #pragma unroll
        for (int ks = 0; ks < 2; ks++) {
            u32 ah[4][4], al[4][4], bh[4], bl[4];
            #pragma unroll
            for (int mi = 0; mi < 4; mi++) {
                ldsm4(ah[mi], sb + OFF_AH + a_off + (u32)(mi * 16 * PITCH) + (u32)(ks * 32));
                ldsm4(al[mi], sb + OFF_AL + a_off + (u32)(mi * 16 * PITCH) + (u32)(ks * 32));
            }
            ldsm4(bh, sb + OFF_BH + b_off + (u32)(ks * 32));
            ldsm4(bl, sb + OFF_BL + b_off + (u32)(ks * 32));
            #pragma unroll
            for (int mi = 0; mi < 4; mi++) {
                #pragma unroll
                for (int ni = 0; ni < 2; ni++) {
                    const int s = ni * 2;
                    mma16816(acc[mi][ni], ah[mi], bh[s], bh[s + 1]);
                    mma16816(acc[mi][ni], ah[mi], bl[s], bl[s + 1]);
                    mma16816(acc[mi][ni], al[mi], bh[s], bh[s + 1]);
                }
            }
        }
    }
    __syncthreads();

    // ---- epilogue: exchange via smem (128 x 132 f32), silu(g)*u, split hi/lo ----
    // gate warps (wn<4) own S cols 0..63; up warps (wn>=4) own S cols 64..127.
    float* S = (float*)dsm;
    #pragma unroll
    for (int mi = 0; mi < 4; mi++) {
        const int rr = wm * 64 + mi * 16 + (lane >> 2);
        #pragma unroll
        for (int ni = 0; ni < 2; ni++) {
            const int cc = wn * 16 + ni * 8 + 2 * (lane & 3);   // 0..127
            *(float2*)(S + (size_t)rr * 132 + cc) =
                make_float2(acc[mi][ni][0], acc[mi][ni][1]);
            *(float2*)(S + (size_t)(rr + 8) * 132 + cc) =
                make_float2(acc[mi][ni][2], acc[mi][ni][3]);
        }
    }
    __syncthreads();
    {
        const int row = tid >> 2;            // 0..127
        const int seg = (tid & 3) * 16;      // 16 inter cols per thread (FIX)
        if (row < rows) {
            u32 ph[8], pl[8];
            #pragma unroll
            for (int p = 0; p < 8; p++) {
                float g0 = S[(size_t)row * 132 + seg + 2 * p];
                float g1 = S[(size_t)row * 132 + seg + 2 * p + 1];
                float u0 = S[(size_t)row * 132 + 64 + seg + 2 * p];
                float u1 = S[(size_t)row * 132 + 64 + seg + 2 * p + 1];
                float h0 = (g0 / (1.0f + expf(-g0))) * u0;
                float h1 = (g1 / (1.0f + expf(-g1))) * u1;
                __nv_bfloat162 A = __floats2bfloat162_rn(h0, h1);
                __nv_bfloat162 B = __floats2bfloat162_rn(h0 - __low2float(A), h1 - __high2float(A));
                ph[p] = *(u32*)&A;
                pl[p] = *(u32*)&B;
            }
            u32* dh = (u32*)(g_Hh + (size_t)(base + row) * INTER + n0 + seg);
            u32* dl = (u32*)(g_Hl + (size_t)(base + row) * INTER + n0 + seg);
            ((uint4*)dh)[0] = make_uint4(ph[0], ph[1], ph[2], ph[3]);
            ((uint4*)dh)[1] = make_uint4(ph[4], ph[5], ph[6], ph[7]);
            ((uint4*)dl)[0] = make_uint4(pl[0], pl[1], pl[2], pl[3]);
            ((uint4*)dl)[1] = make_uint4(pl[4], pl[5], pl[6], pl[7]);
        }
    }
}

// ---- GEMM 2: down. CTA: 128 slots x 128 hid, 512 thr, K=1024 ---------------------
__global__ __launch_bounds__(512, 1) void down_mma_kernel() {
    const int e   = blockIdx.z;
    const int cnt = g_cnt[e];
    const int m0  = blockIdx.y * 128;
    if (m0 >= cnt) return;
    const int rows = min(cnt - m0, 128);
    const int base = g_off[e] + m0;
    const int n0   = blockIdx.x * 128;

    extern __shared__ char dsm[];
    const u32 sm0 = smem_u32(dsm);

    const int tid  = threadIdx.x;
    const int lane = tid & 31;
    const int wid  = tid >> 5;
    const int wm   = wid >> 3;
    const int wn   = wid & 7;           // 0..7 -> 16 hid cols

    const int u = tid & 127;
    const int v = tid >> 7;
    const __nv_bfloat16* p0;
    if (v < 2) {
        const int ra = min(u, rows - 1);
        p0 = (v ? g_Hl : g_Hh) + (size_t)(base + ra) * INTER;
    } else {
        p0 = (v == 2 ? g_Wdh : g_Wdl) + ((size_t)e * HID + n0 + u) * INTER;
    }
    const u32 offv = (v == 0) ? OFF_AH : (v == 1) ? OFF_AL : (v == 2) ? OFF_BH : OFF_BL;
    const u32 d0 = offv + (u32)u * PITCH;

    const u32 a_off = (u32)((wm * 64 + (lane & 7) + ((lane >> 3) & 1) * 8) * PITCH
                    + (lane >> 4) * 16);
    const u32 b_off = (u32)((wn * 16 + (lane & 7) + (lane >> 4) * 8) * PITCH
                    + ((lane >> 3) & 1) * 16);

    float acc[4][2][4];
    #pragma unroll
    for (int i = 0; i < 4; i++)
        #pragma unroll
        for (int j = 0; j < 2; j++)
            #pragma unroll
            for (int k = 0; k < 4; k++) acc[i][j][k] = 0.0f;

    const int KT = INTER / 32;          // 32

    #pragma unroll
    for (int p = 0; p < NSTAGE - 1; p++) {
        const u32 sb = sm0 + (u32)p * STAGE_BYTES;
        const size_t ko = (size_t)p * 32;
        #pragma unroll
        for (int c = 0; c < 4; c++) cpa16(sb + d0 + c * 16, p0 + ko + c * 8);
        CPA_COMMIT();
    }

    #pragma unroll 1
    for (int kt = 0; kt < KT; kt++) {
        if (kt == KT - 1) CPA_WAIT0(); else CPA_WAIT1();
        __syncthreads();
        if (kt + NSTAGE - 1 < KT) {
            const u32 sb = sm0 + (u32)((kt + NSTAGE - 1) % NSTAGE) * STAGE_BYTES;
            const size_t ko = (size_t)(kt + NSTAGE - 1) * 32;
            #pragma unroll
            for (int c = 0; c < 4; c++) cpa16(sb + d0 + c * 16, p0 + ko + c * 8);
            CPA_COMMIT();
        }
        const u32 sb = sm0 + (u32)(kt % NSTAGE) * STAGE_BYTES;
        #pragma unroll
        for (int ks = 0; ks < 2; ks++) {
            u32 ah[4][4], al[4][4], bh[4], bl[4];
            #pragma unroll
            for (int mi = 0; mi < 4; mi++) {
                ldsm4(ah[mi], sb + OFF_AH + a_off + (u32)(mi * 16 * PITCH) + (u32)(ks * 32));
                ldsm4(al[mi], sb + OFF_AL + a_off + (u32)(mi * 16 * PITCH) + (u32)(ks * 32));
            }
            ldsm4(bh, sb + OFF_BH + b_off + (u32)(ks * 32));
            ldsm4(bl, sb + OFF_BL + b_off + (u32)(ks * 32));
            #pragma unroll
            for (int mi = 0; mi < 4; mi++) {
                #pragma unroll
                for (int ni = 0; ni < 2; ni++) {
                    const int s = ni * 2;
                    mma16816(acc[mi][ni], ah[mi], bh[s], bh[s + 1]);
                    mma16816(acc[mi][ni], ah[mi], bl[s], bl[s + 1]);
                    mma16816(acc[mi][ni], al[mi], bh[s], bh[s + 1]);
                }
            }
        }
    }

    // ---- epilogue: scale by routing weight, store f32 ----
    #pragma unroll
    for (int mi = 0; mi < 4; mi++) {
        const int r0o = wm * 64 + mi * 16 + (lane >> 2);
        const int r1o = r0o + 8;
        #pragma unroll
        for (int ni = 0; ni < 2; ni++) {
            const int cc = n0 + wn * 16 + ni * 8 + 2 * (lane & 3);
            if (r0o < rows) {
                const float w0 = g_w[base + r0o];
                *(float2*)(g_y + (size_t)(base + r0o) * HID + cc) =
                    make_float2(w0 * acc[mi][ni][0], w0 * acc[mi][ni][1]);
            }
            if (r1o < rows) {
                const float w1 = g_w[base + r1o];
                *(float2*)(g_y + (size_t)(base + r1o) * HID + cc) =
                    make_float2(w1 * acc[mi][ni][2], w1 * acc[mi][ni][3]);
            }
        }
    }
}

// ---- combine: out[t] = y[slot0] + y[slot1] ----------------------------------------
__global__ void combine_kernel(float* __restrict__ out, int T) {
    const int gid = blockIdx.x * blockDim.x + threadIdx.x;
    const int per_tok = HID / 4;
    if (gid >= T * per_tok) return;
    const int t = gid / per_tok;
    const int c = gid - t * per_tok;
    const int s0 = g_slot_of[2 * t];
    const int s1 = g_slot_of[2 * t + 1];
    float4 a = ((const float4*)(g_y + (size_t)s0 * HID))[c];
    float4 b = ((const float4*)(g_y + (size_t)s1 * HID))[c];
    ((float4*)(out + (size_t)t * HID))[c] =
        make_float4(a.x + b.x, a.y + b.y, a.z + b.z, a.w + b.w);
}

// ---- launch -------------------------------------------------------------------------
extern "C" void kernel_launch(void* const* d_in, const int* in_sizes, int n_in,
                              void* d_out, int out_size) {
    if (n_in < 5) return;
    const float* x  = (const float*)d_in[0];
    const float* Wr = (const float*)d_in[1];
    const float* Wg = (const float*)d_in[2];
    const float* Wu = (const float*)d_in[3];
    const float* Wd = (const float*)d_in[4];
    float* out = (float*)d_out;

    int T = in_sizes[0] / HID;
    if (T > MAXT) T = MAXT;

    cudaFuncSetAttribute(gateup_mma_kernel, cudaFuncAttributeMaxDynamicSharedMemorySize, SMEM_DYN);
    cudaFuncSetAttribute(down_mma_kernel,   cudaFuncAttributeMaxDynamicSharedMemorySize, SMEM_DYN);

    const int write_logits = (out_size >= T * HID + T * NEXP);
    float* logits = out + (size_t)T * HID;

    zero_counters_kernel<<<1, 32>>>();
    router_kernel<<<T, 256>>>(x, Wr, logits, write_logits);
    offsets_kernel<<<1, 32>>>();
    scatter_kernel<<<(T + 255) / 256, 256>>>(T);

    const int nx = T * HID / 4;
    const int nw = NEXP * INTER * HID / 4;
    split_all_kernel<<<(nx + 3 * nw + 255) / 256, 256>>>(x, Wg, Wu, Wd, nx, nw);

    gateup_mma_kernel<<<dim3(INTER / 64, MAXSLOTS / 128, NEXP), 512, SMEM_DYN>>>();
    down_mma_kernel<<<dim3(HID / 128, MAXSLOTS / 128, NEXP), 512, SMEM_DYN>>>();

    combine_kernel<<<(T * (HID / 4) + 255) / 256, 256>>>(out, T);
}

// round 8
// speedup vs baseline: 1.5657x; 1.5657x over previous
#include <cuda_runtime.h>
#include <cuda_fp16.h>
#include <cstdint>

// ============================================================================
// BiBoSparseMoeBlock: top-2-of-8 MoE SwiGLU, fp32 in/out.
// Round 8: round-4 champion skeleton, but fp16 2-term split:
//   A = ah + al (fp16 pair), B = single fp16  ->  2 MMAs per k-step (was 3).
// ============================================================================

#define HID   2048
#define INTER 1024
#define NEXP  8
#define MAXT  4096
#define MAXSLOTS (2 * MAXT)

typedef unsigned int u32;

// ---- device scratch ---------------------------------------------------------
__device__ int   g_cnt[NEXP];
__device__ int   g_off[NEXP];
__device__ int   g_fill[NEXP];
__device__ int   g_perm[MAXSLOTS];
__device__ float g_w[MAXSLOTS];
__device__ int   g_tidx[MAXT * 2];
__device__ float g_tw[MAXT * 2];
__device__ int   g_slot_of[MAXT * 2];

__device__ __half g_Xh[(size_t)MAXT * HID];
__device__ __half g_Xl[(size_t)MAXT * HID];
__device__ __half g_Wg16[(size_t)NEXP * INTER * HID];
__device__ __half g_Wu16[(size_t)NEXP * INTER * HID];
__device__ __half g_Wd16[(size_t)NEXP * HID * INTER];
__device__ __half g_Hh[(size_t)MAXSLOTS * INTER];
__device__ __half g_Hl[(size_t)MAXSLOTS * INTER];
__device__ float  g_y[(size_t)MAXSLOTS * HID];

// ---- PTX helpers (baseline sm_80-era only) -------------------------------------
__device__ __forceinline__ u32 smem_u32(const void* p) {
    u32 a;
    asm("{ .reg .u64 t; cvta.to.shared.u64 t, %1; cvt.u32.u64 %0, t; }" : "=r"(a) : "l"(p));
    return a;
}
__device__ __forceinline__ void cpa16(u32 dst, const void* src) {
    asm volatile("cp.async.cg.shared.global [%0], [%1], 16;" :: "r"(dst), "l"(src));
}
#define CPA_COMMIT() asm volatile("cp.async.commit_group;" ::: "memory")
#define CPA_WAIT1()  asm volatile("cp.async.wait_group 1;" ::: "memory")
#define CPA_WAIT0()  asm volatile("cp.async.wait_group 0;" ::: "memory")

__device__ __forceinline__ void ldsm4(u32* r, u32 addr) {
    asm volatile("ldmatrix.sync.aligned.m8n8.x4.shared.b16 {%0,%1,%2,%3}, [%4];"
                 : "=r"(r[0]), "=r"(r[1]), "=r"(r[2]), "=r"(r[3]) : "r"(addr));
}
__device__ __forceinline__ void mma16816(float* c, const u32* a, u32 b0, u32 b1) {
    asm volatile(
        "mma.sync.aligned.m16n8k16.row.col.f32.f16.f16.f32 "
        "{%0,%1,%2,%3}, {%4,%5,%6,%7}, {%8,%9}, {%0,%1,%2,%3};"
        : "+f"(c[0]), "+f"(c[1]), "+f"(c[2]), "+f"(c[3])
        : "r"(a[0]), "r"(a[1]), "r"(a[2]), "r"(a[3]), "r"(b0), "r"(b1));
}

// ---- smem geometry: BK=32 fp16 rows (64B data), pitch 80B ----------------------
#define PITCH 80
#define OFF_AH 0
#define OFF_AL 10240          // 128 rows * 80
#define OFF_B  20480          // 64 rows * 80 (single B matrix)
#define STAGE_BYTES 25600
#define NSTAGE 3
#define SMEM_DYN (NSTAGE * STAGE_BYTES)   // 76800 -> 2 CTAs/SM

// ---- small kernels --------------------------------------------------------------
__global__ void zero_counters_kernel() {
    int i = threadIdx.x;
    if (i < NEXP) { g_cnt[i] = 0; g_fill[i] = 0; }
}

__global__ void router_kernel(const float* __restrict__ x,
                              const float* __restrict__ Wr,
                              float* __restrict__ logits_out, int write_logits) {
    const int t = blockIdx.x;
    const int warp = threadIdx.x >> 5;
    const int lane = threadIdx.x & 31;
    __shared__ float slog[NEXP];
    const float* xr = x + (size_t)t * HID;
    const float* wr = Wr + (size_t)warp * HID;
    float s = 0.0f;
    #pragma unroll 4
    for (int i = lane; i < HID; i += 32) s += xr[i] * wr[i];
    #pragma unroll
    for (int o = 16; o > 0; o >>= 1) s += __shfl_xor_sync(0xffffffffu, s, o);
    if (lane == 0) slog[warp] = s;
    __syncthreads();
    if (write_logits && threadIdx.x < NEXP)
        logits_out[t * NEXP + threadIdx.x] = slog[threadIdx.x];
    if (threadIdx.x == 0) {
        float v0 = -1e30f; int i0 = 0;
        #pragma unroll
        for (int i = 0; i < NEXP; i++) if (slog[i] > v0) { v0 = slog[i]; i0 = i; }
        float v1 = -1e30f; int i1 = 0;
        #pragma unroll
        for (int i = 0; i < NEXP; i++)
            if (i != i0 && slog[i] > v1) { v1 = slog[i]; i1 = i; }
        float ex = expf(v1 - v0);
        float inv = 1.0f / (1.0f + ex);
        g_tidx[2 * t] = i0; g_tidx[2 * t + 1] = i1;
        g_tw[2 * t] = inv;  g_tw[2 * t + 1] = ex * inv;
        atomicAdd(&g_cnt[i0], 1);
        atomicAdd(&g_cnt[i1], 1);
    }
}

__global__ void offsets_kernel() {
    if (threadIdx.x == 0) {
        int o = 0;
        #pragma unroll
        for (int e = 0; e < NEXP; e++) { g_off[e] = o; o += g_cnt[e]; }
    }
}

__global__ void scatter_kernel(int T) {
    int t = blockIdx.x * blockDim.x + threadIdx.x;
    if (t >= T) return;
    #pragma unroll
    for (int j = 0; j < 2; j++) {
        int e = g_tidx[2 * t + j];
        int p = atomicAdd(&g_fill[e], 1);
        int slot = g_off[e] + p;
        g_perm[slot] = t;
        g_w[slot] = g_tw[2 * t + j];
        g_slot_of[2 * t + j] = slot;
    }
}

// ---- conversion pre-pass ---------------------------------------------------------
__device__ __forceinline__ uint2 f4_to_h4(const float4 v) {
    __half2 a = __floats2half2_rn(v.x, v.y);
    __half2 b = __floats2half2_rn(v.z, v.w);
    return make_uint2(*(u32*)&a, *(u32*)&b);
}

// X: fp32 -> fp16 (hi, lo). Weights: fp32 -> fp16 (single).
__global__ void split_all_kernel(const float* __restrict__ x,
                                 const float* __restrict__ Wg,
                                 const float* __restrict__ Wu,
                                 const float* __restrict__ Wd, int nx, int nw) {
    int i = blockIdx.x * blockDim.x + threadIdx.x;
    if (i < nx) {
        float4 v = ((const float4*)x)[i];
        __half2 A = __floats2half2_rn(v.x, v.y);
        __half2 B = __floats2half2_rn(v.z, v.w);
        __half2 Ar = __floats2half2_rn(v.x - __low2float(A), v.y - __high2float(A));
        __half2 Br = __floats2half2_rn(v.z - __low2float(B), v.w - __high2float(B));
        ((uint2*)g_Xh)[i] = make_uint2(*(u32*)&A, *(u32*)&B);
        ((uint2*)g_Xl)[i] = make_uint2(*(u32*)&Ar, *(u32*)&Br);
    } else if (i < nx + nw) {
        int j = i - nx;
        ((uint2*)g_Wg16)[j] = f4_to_h4(((const float4*)Wg)[j]);
    } else if (i < nx + 2 * nw) {
        int j = i - nx - nw;
        ((uint2*)g_Wu16)[j] = f4_to_h4(((const float4*)Wu)[j]);
    } else if (i < nx + 3 * nw) {
        int j = i - nx - 2 * nw;
        ((uint2*)g_Wd16)[j] = f4_to_h4(((const float4*)Wd)[j]);
    }
}

// ---- GEMM 1: gate+up. CTA: 128 slots x 32 inter (gate+up => 64 B-rows), K=2048 ---
__global__ __launch_bounds__(256, 2) void gateup_mma_kernel() {
    const int e   = blockIdx.z;
    const int cnt = g_cnt[e];
    const int m0  = blockIdx.y * 128;
    if (m0 >= cnt) return;
    const int rows = min(cnt - m0, 128);
    const int base = g_off[e] + m0;
    const int n0   = blockIdx.x * 32;

    extern __shared__ char dsm[];
    const u32 sm0 = smem_u32(dsm);

    const int tid  = threadIdx.x;
    const int lane = tid & 31;
    const int wid  = tid >> 5;
    const int wm   = wid >> 2;          // 0..1 -> 64-row half
    const int wn   = wid & 3;           // 0..3 -> 16 B-rows

    // ---- loader mapping: q = row, c = 16B chunk; 5 cp.async / thread / stage ----
    const int q = tid >> 2;             // 0..63
    const int c = tid & 3;
    const int r0 = min(q, rows - 1);
    const int r1 = min(q + 64, rows - 1);
    const size_t xo0 = (size_t)g_perm[base + r0] * HID + c * 8;
    const size_t xo1 = (size_t)g_perm[base + r1] * HID + c * 8;
    const __half* pb;
    if (q < 32) pb = g_Wg16 + ((size_t)e * INTER + n0 + q) * HID + c * 8;
    else        pb = g_Wu16 + ((size_t)e * INTER + n0 + (q - 32)) * HID + c * 8;

    const u32 dA0 = (u32)(OFF_AH + q * PITCH + c * 16);
    const u32 dA1 = dA0 + 64 * PITCH;
    const u32 dL0 = dA0 + (OFF_AL - OFF_AH);
    const u32 dL1 = dA1 + (OFF_AL - OFF_AH);
    const u32 dB  = (u32)(OFF_B + q * PITCH + c * 16);

    // ---- ldmatrix bases ----
    const u32 a_off = (u32)((wm * 64 + (lane & 7) + ((lane >> 3) & 1) * 8) * PITCH
                    + (lane >> 4) * 16);
    const u32 b_off = (u32)((wn * 16 + (lane & 7) + (lane >> 4) * 8) * PITCH
                    + ((lane >> 3) & 1) * 16);

    float acc[4][2][4];
    #pragma unroll
    for (int i = 0; i < 4; i++)
        #pragma unroll
        for (int j = 0; j < 2; j++)
            #pragma unroll
            for (int k = 0; k < 4; k++) acc[i][j][k] = 0.0f;

    const int KT = HID / 32;            // 64

    #pragma unroll
    for (int p = 0; p < NSTAGE - 1; p++) {
        const u32 sb = sm0 + (u32)p * STAGE_BYTES;
        const size_t ko = (size_t)p * 32;
        cpa16(sb + dA0, g_Xh + xo0 + ko);
        cpa16(sb + dA1, g_Xh + xo1 + ko);
        cpa16(sb + dL0, g_Xl + xo0 + ko);
        cpa16(sb + dL1, g_Xl + xo1 + ko);
        cpa16(sb + dB,  pb + ko);
        CPA_COMMIT();
    }

    #pragma unroll 1
    for (int kt = 0; kt < KT; kt++) {
        if (kt == KT - 1) CPA_WAIT0(); else CPA_WAIT1();
        __syncthreads();
        if (kt + NSTAGE - 1 < KT) {
            const u32 sb = sm0 + (u32)((kt + NSTAGE - 1) % NSTAGE) * STAGE_BYTES;
            const size_t ko = (size_t)(kt + NSTAGE - 1) * 32;
            cpa16(sb + dA0, g_Xh + xo0 + ko);
            cpa16(sb + dA1, g_Xh + xo1 + ko);
            cpa16(sb + dL0, g_Xl + xo0 + ko);
            cpa16(sb + dL1, g_Xl + xo1 + ko);
            cpa16(sb + dB,  pb + ko);
            CPA_COMMIT();
        }
        const u32 sb = sm0 + (u32)(kt % NSTAGE) * STAGE_BYTES;
        #pragma unroll
        for (int ks = 0; ks < 2; ks++) {
            u32 ah[4][4], al[4][4], bh[4];
            #pragma unroll
            for (int mi = 0; mi < 4; mi++) {
                ldsm4(ah[mi], sb + OFF_AH + a_off + (u32)(mi * 16 * PITCH) + (u32)(ks * 32));
                ldsm4(al[mi], sb + OFF_AL + a_off + (u32)(mi * 16 * PITCH) + (u32)(ks * 32));
            }
            ldsm4(bh, sb + OFF_B + b_off + (u32)(ks * 32));
            #pragma unroll
            for (int mi = 0; mi < 4; mi++) {
                #pragma unroll
                for (int ni = 0; ni < 2; ni++) {
                    const int s = ni * 2;
                    mma16816(acc[mi][ni], ah[mi], bh[s], bh[s + 1]);
                    mma16816(acc[mi][ni], al[mi], bh[s], bh[s + 1]);
                }
            }
        }
    }
    __syncthreads();

    // ---- epilogue: exchange via smem (128 x 72 f32), silu(g)*u, split hi/lo ----
    float* S = (float*)dsm;
    #pragma unroll
    for (int mi = 0; mi < 4; mi++) {
        const int rr = wm * 64 + mi * 16 + (lane >> 2);
        #pragma unroll
        for (int ni = 0; ni < 2; ni++) {
            const int cc = wn * 16 + ni * 8 + 2 * (lane & 3);
            *(float2*)(S + (size_t)rr * 72 + cc)       = make_float2(acc[mi][ni][0], acc[mi][ni][1]);
            *(float2*)(S + (size_t)(rr + 8) * 72 + cc) = make_float2(acc[mi][ni][2], acc[mi][ni][3]);
        }
    }
    __syncthreads();
    {
        const int row  = tid >> 1;
        const int half = (tid & 1) * 16;
        if (row < rows) {
            u32 ph[8], pl[8];
            #pragma unroll
            for (int p = 0; p < 8; p++) {
                float g0 = S[(size_t)row * 72 + half + 2 * p];
                float g1 = S[(size_t)row * 72 + half + 2 * p + 1];
                float u0 = S[(size_t)row * 72 + 32 + half + 2 * p];
                float u1 = S[(size_t)row * 72 + 32 + half + 2 * p + 1];
                float h0 = (g0 / (1.0f + expf(-g0))) * u0;
                float h1 = (g1 / (1.0f + expf(-g1))) * u1;
                __half2 A = __floats2half2_rn(h0, h1);
                __half2 B = __floats2half2_rn(h0 - __low2float(A), h1 - __high2float(A));
                ph[p] = *(u32*)&A;
                pl[p] = *(u32*)&B;
            }
            u32* dh = (u32*)(g_Hh + (size_t)(base + row) * INTER + n0 + half);
            u32* dl = (u32*)(g_Hl + (size_t)(base + row) * INTER + n0 + half);
            ((uint4*)dh)[0] = make_uint4(ph[0], ph[1], ph[2], ph[3]);
            ((uint4*)dh)[1] = make_uint4(ph[4], ph[5], ph[6], ph[7]);
            ((uint4*)dl)[0] = make_uint4(pl[0], pl[1], pl[2], pl[3]);
            ((uint4*)dl)[1] = make_uint4(pl[4], pl[5], pl[6], pl[7]);
        }
    }
}

// ---- GEMM 2: down. CTA: 128 slots x 64 hid, K=1024 -------------------------------
__global__ __launch_bounds__(256, 2) void down_mma_kernel() {
    const int e   = blockIdx.z;
    const int cnt = g_cnt[e];
    const int m0  = blockIdx.y * 128;
    if (m0 >= cnt) return;
    const int rows = min(cnt - m0, 128);
    const int base = g_off[e] + m0;
    const int n0   = blockIdx.x * 64;

    extern __shared__ char dsm[];
    const u32 sm0 = smem_u32(dsm);

    const int tid  = threadIdx.x;
    const int lane = tid & 31;
    const int wid  = tid >> 5;
    const int wm   = wid >> 2;
    const int wn   = wid & 3;

    const int q = tid >> 2;
    const int c = tid & 3;
    const int r0 = min(q, rows - 1);
    const int r1 = min(q + 64, rows - 1);
    const size_t ho0 = (size_t)(base + r0) * INTER + c * 8;
    const size_t ho1 = (size_t)(base + r1) * INTER + c * 8;
    const __half* pb = g_Wd16 + ((size_t)e * HID + n0 + q) * INTER + c * 8;

    const u32 dA0 = (u32)(OFF_AH + q * PITCH + c * 16);
    const u32 dA1 = dA0 + 64 * PITCH;
    const u32 dL0 = dA0 + (OFF_AL - OFF_AH);
    const u32 dL1 = dA1 + (OFF_AL - OFF_AH);
    const u32 dB  = (u32)(OFF_B + q * PITCH + c * 16);

    const u32 a_off = (u32)((wm * 64 + (lane & 7) + ((lane >> 3) & 1) * 8) * PITCH
                    + (lane >> 4) * 16);
    const u32 b_off = (u32)((wn * 16 + (lane & 7) + (lane >> 4) * 8) * PITCH
                    + ((lane >> 3) & 1) * 16);

    float acc[4][2][4];
    #pragma unroll
    for (int i = 0; i < 4; i++)
        #pragma unroll
        for (int j = 0; j < 2; j++)
            #pragma unroll
            for (int k = 0; k < 4; k++) acc[i][j][k] = 0.0f;

    const int KT = INTER / 32;          // 32

    #pragma unroll
    for (int p = 0; p < NSTAGE - 1; p++) {
        const u32 sb = sm0 + (u32)p * STAGE_BYTES;
        const size_t ko = (size_t)p * 32;
        cpa16(sb + dA0, g_Hh + ho0 + ko);
        cpa16(sb + dA1, g_Hh + ho1 + ko);
        cpa16(sb + dL0, g_Hl + ho0 + ko);
        cpa16(sb + dL1, g_Hl + ho1 + ko);
        cpa16(sb + dB,  pb + ko);
        CPA_COMMIT();
    }

    #pragma unroll 1
    for (int kt = 0; kt < KT; kt++) {
        if (kt == KT - 1) CPA_WAIT0(); else CPA_WAIT1();
        __syncthreads();
        if (kt + NSTAGE - 1 < KT) {
            const u32 sb = sm0 + (u32)((kt + NSTAGE - 1) % NSTAGE) * STAGE_BYTES;
            const size_t ko = (size_t)(kt + NSTAGE - 1) * 32;
            cpa16(sb + dA0, g_Hh + ho0 + ko);
            cpa16(sb + dA1, g_Hh + ho1 + ko);
            cpa16(sb + dL0, g_Hl + ho0 + ko);
            cpa16(sb + dL1, g_Hl + ho1 + ko);
            cpa16(sb + dB,  pb + ko);
            CPA_COMMIT();
        }
        const u32 sb = sm0 + (u32)(kt % NSTAGE) * STAGE_BYTES;
        #pragma unroll
        for (int ks = 0; ks < 2; ks++) {
            u32 ah[4][4], al[4][4], bh[4];
            #pragma unroll
            for (int mi = 0; mi < 4; mi++) {
                ldsm4(ah[mi], sb + OFF_AH + a_off + (u32)(mi * 16 * PITCH) + (u32)(ks * 32));
                ldsm4(al[mi], sb + OFF_AL + a_off + (u32)(mi * 16 * PITCH) + (u32)(ks * 32));
            }
            ldsm4(bh, sb + OFF_B + b_off + (u32)(ks * 32));
            #pragma unroll
            for (int mi = 0; mi < 4; mi++) {
                #pragma unroll
                for (int ni = 0; ni < 2; ni++) {
                    const int s = ni * 2;
                    mma16816(acc[mi][ni], ah[mi], bh[s], bh[s + 1]);
                    mma16816(acc[mi][ni], al[mi], bh[s], bh[s + 1]);
                }
            }
        }
    }

    // ---- epilogue: scale by routing weight, store f32 ----
    #pragma unroll
    for (int mi = 0; mi < 4; mi++) {
        const int r0o = wm * 64 + mi * 16 + (lane >> 2);
        const int r1o = r0o + 8;
        #pragma unroll
        for (int ni = 0; ni < 2; ni++) {
            const int cc = n0 + wn * 16 + ni * 8 + 2 * (lane & 3);
            if (r0o < rows) {
                const float w0 = g_w[base + r0o];
                *(float2*)(g_y + (size_t)(base + r0o) * HID + cc) =
                    make_float2(w0 * acc[mi][ni][0], w0 * acc[mi][ni][1]);
            }
            if (r1o < rows) {
                const float w1 = g_w[base + r1o];
                *(float2*)(g_y + (size_t)(base + r1o) * HID + cc) =
                    make_float2(w1 * acc[mi][ni][2], w1 * acc[mi][ni][3]);
            }
        }
    }
}

// ---- combine: out[t] = y[slot0] + y[slot1] ----------------------------------------
__global__ void combine_kernel(float* __restrict__ out, int T) {
    const int gid = blockIdx.x * blockDim.x + threadIdx.x;
    const int per_tok = HID / 4;
    if (gid >= T * per_tok) return;
    const int t = gid / per_tok;
    const int c = gid - t * per_tok;
    const int s0 = g_slot_of[2 * t];
    const int s1 = g_slot_of[2 * t + 1];
    float4 a = ((const float4*)(g_y + (size_t)s0 * HID))[c];
    float4 b = ((const float4*)(g_y + (size_t)s1 * HID))[c];
    ((float4*)(out + (size_t)t * HID))[c] =
        make_float4(a.x + b.x, a.y + b.y, a.z + b.z, a.w + b.w);
}

// ---- launch -------------------------------------------------------------------------
extern "C" void kernel_launch(void* const* d_in, const int* in_sizes, int n_in,
                              void* d_out, int out_size) {
    if (n_in < 5) return;
    const float* x  = (const float*)d_in[0];
    const float* Wr = (const float*)d_in[1];
    const float* Wg = (const float*)d_in[2];
    const float* Wu = (const float*)d_in[3];
    const float* Wd = (const float*)d_in[4];
    float* out = (float*)d_out;

    int T = in_sizes[0] / HID;
    if (T > MAXT) T = MAXT;

    cudaFuncSetAttribute(gateup_mma_kernel, cudaFuncAttributeMaxDynamicSharedMemorySize, SMEM_DYN);
    cudaFuncSetAttribute(down_mma_kernel,   cudaFuncAttributeMaxDynamicSharedMemorySize, SMEM_DYN);

    const int write_logits = (out_size >= T * HID + T * NEXP);
    float* logits = out + (size_t)T * HID;

    zero_counters_kernel<<<1, 32>>>();
    router_kernel<<<T, 256>>>(x, Wr, logits, write_logits);
    offsets_kernel<<<1, 32>>>();
    scatter_kernel<<<(T + 255) / 256, 256>>>(T);

    const int nx = T * HID / 4;
    const int nw = NEXP * INTER * HID / 4;
    split_all_kernel<<<(nx + 3 * nw + 255) / 256, 256>>>(x, Wg, Wu, Wd, nx, nw);

    gateup_mma_kernel<<<dim3(INTER / 32, MAXSLOTS / 128, NEXP), 256, SMEM_DYN>>>();
    down_mma_kernel<<<dim3(HID / 64, MAXSLOTS / 128, NEXP), 256, SMEM_DYN>>>();

    combine_kernel<<<(T * (HID / 4) + 255) / 256, 256>>>(out, T);
}

// round 9
// speedup vs baseline: 1.7782x; 1.1357x over previous
#include <cuda_runtime.h>
#include <cuda_fp16.h>
#include <cstdint>

// ============================================================================
// BiBoSparseMoeBlock: top-2-of-8 MoE SwiGLU, fp32 in/out.
// Round 9: fp16 2-term split (A=hi+lo, B single), 32x32 warp tiles to halve
// LDSM fragment traffic (was 64x16). Same CTA tiles/pipeline as round 8.
// ============================================================================

#define HID   2048
#define INTER 1024
#define NEXP  8
#define MAXT  4096
#define MAXSLOTS (2 * MAXT)

typedef unsigned int u32;

// ---- device scratch ---------------------------------------------------------
__device__ int   g_cnt[NEXP];
__device__ int   g_off[NEXP];
__device__ int   g_fill[NEXP];
__device__ int   g_perm[MAXSLOTS];
__device__ float g_w[MAXSLOTS];
__device__ int   g_tidx[MAXT * 2];
__device__ float g_tw[MAXT * 2];
__device__ int   g_slot_of[MAXT * 2];

__device__ __half g_Xh[(size_t)MAXT * HID];
__device__ __half g_Xl[(size_t)MAXT * HID];
__device__ __half g_Wg16[(size_t)NEXP * INTER * HID];
__device__ __half g_Wu16[(size_t)NEXP * INTER * HID];
__device__ __half g_Wd16[(size_t)NEXP * HID * INTER];
__device__ __half g_Hh[(size_t)MAXSLOTS * INTER];
__device__ __half g_Hl[(size_t)MAXSLOTS * INTER];
__device__ float  g_y[(size_t)MAXSLOTS * HID];

// ---- PTX helpers (baseline sm_80-era only) -------------------------------------
__device__ __forceinline__ u32 smem_u32(const void* p) {
    u32 a;
    asm("{ .reg .u64 t; cvta.to.shared.u64 t, %1; cvt.u32.u64 %0, t; }" : "=r"(a) : "l"(p));
    return a;
}
__device__ __forceinline__ void cpa16(u32 dst, const void* src) {
    asm volatile("cp.async.cg.shared.global [%0], [%1], 16;" :: "r"(dst), "l"(src));
}
#define CPA_COMMIT() asm volatile("cp.async.commit_group;" ::: "memory")
#define CPA_WAIT1()  asm volatile("cp.async.wait_group 1;" ::: "memory")
#define CPA_WAIT0()  asm volatile("cp.async.wait_group 0;" ::: "memory")

__device__ __forceinline__ void ldsm4(u32* r, u32 addr) {
    asm volatile("ldmatrix.sync.aligned.m8n8.x4.shared.b16 {%0,%1,%2,%3}, [%4];"
                 : "=r"(r[0]), "=r"(r[1]), "=r"(r[2]), "=r"(r[3]) : "r"(addr));
}
__device__ __forceinline__ void mma16816(float* c, const u32* a, u32 b0, u32 b1) {
    asm volatile(
        "mma.sync.aligned.m16n8k16.row.col.f32.f16.f16.f32 "
        "{%0,%1,%2,%3}, {%4,%5,%6,%7}, {%8,%9}, {%0,%1,%2,%3};"
        : "+f"(c[0]), "+f"(c[1]), "+f"(c[2]), "+f"(c[3])
        : "r"(a[0]), "r"(a[1]), "r"(a[2]), "r"(a[3]), "r"(b0), "r"(b1));
}

// ---- smem geometry: BK=32 fp16 rows (64B data), pitch 80B ----------------------
#define PITCH 80
#define OFF_AH 0
#define OFF_AL 10240          // 128 rows * 80
#define OFF_B  20480          // 64 rows * 80 (single B matrix)
#define STAGE_BYTES 25600
#define NSTAGE 3
#define SMEM_DYN (NSTAGE * STAGE_BYTES)   // 76800 -> 2 CTAs/SM

// ---- small kernels --------------------------------------------------------------
__global__ void zero_counters_kernel() {
    int i = threadIdx.x;
    if (i < NEXP) { g_cnt[i] = 0; g_fill[i] = 0; }
}

__global__ void router_kernel(const float* __restrict__ x,
                              const float* __restrict__ Wr,
                              float* __restrict__ logits_out, int write_logits) {
    const int t = blockIdx.x;
    const int warp = threadIdx.x >> 5;
    const int lane = threadIdx.x & 31;
    __shared__ float slog[NEXP];
    const float* xr = x + (size_t)t * HID;
    const float* wr = Wr + (size_t)warp * HID;
    float s = 0.0f;
    #pragma unroll 4
    for (int i = lane; i < HID; i += 32) s += xr[i] * wr[i];
    #pragma unroll
    for (int o = 16; o > 0; o >>= 1) s += __shfl_xor_sync(0xffffffffu, s, o);
    if (lane == 0) slog[warp] = s;
    __syncthreads();
    if (write_logits && threadIdx.x < NEXP)
        logits_out[t * NEXP + threadIdx.x] = slog[threadIdx.x];
    if (threadIdx.x == 0) {
        float v0 = -1e30f; int i0 = 0;
        #pragma unroll
        for (int i = 0; i < NEXP; i++) if (slog[i] > v0) { v0 = slog[i]; i0 = i; }
        float v1 = -1e30f; int i1 = 0;
        #pragma unroll
        for (int i = 0; i < NEXP; i++)
            if (i != i0 && slog[i] > v1) { v1 = slog[i]; i1 = i; }
        float ex = expf(v1 - v0);
        float inv = 1.0f / (1.0f + ex);
        g_tidx[2 * t] = i0; g_tidx[2 * t + 1] = i1;
        g_tw[2 * t] = inv;  g_tw[2 * t + 1] = ex * inv;
        atomicAdd(&g_cnt[i0], 1);
        atomicAdd(&g_cnt[i1], 1);
    }
}

__global__ void offsets_kernel() {
    if (threadIdx.x == 0) {
        int o = 0;
        #pragma unroll
        for (int e = 0; e < NEXP; e++) { g_off[e] = o; o += g_cnt[e]; }
    }
}

__global__ void scatter_kernel(int T) {
    int t = blockIdx.x * blockDim.x + threadIdx.x;
    if (t >= T) return;
    #pragma unroll
    for (int j = 0; j < 2; j++) {
        int e = g_tidx[2 * t + j];
        int p = atomicAdd(&g_fill[e], 1);
        int slot = g_off[e] + p;
        g_perm[slot] = t;
        g_w[slot] = g_tw[2 * t + j];
        g_slot_of[2 * t + j] = slot;
    }
}

// ---- conversion pre-pass ---------------------------------------------------------
__device__ __forceinline__ uint2 f4_to_h4(const float4 v) {
    __half2 a = __floats2half2_rn(v.x, v.y);
    __half2 b = __floats2half2_rn(v.z, v.w);
    return make_uint2(*(u32*)&a, *(u32*)&b);
}

__global__ void split_all_kernel(const float* __restrict__ x,
                                 const float* __restrict__ Wg,
                                 const float* __restrict__ Wu,
                                 const float* __restrict__ Wd, int nx, int nw) {
    int i = blockIdx.x * blockDim.x + threadIdx.x;
    if (i < nx) {
        float4 v = ((const float4*)x)[i];
        __half2 A = __floats2half2_rn(v.x, v.y);
        __half2 B = __floats2half2_rn(v.z, v.w);
        __half2 Ar = __floats2half2_rn(v.x - __low2float(A), v.y - __high2float(A));
        __half2 Br = __floats2half2_rn(v.z - __low2float(B), v.w - __high2float(B));
        ((uint2*)g_Xh)[i] = make_uint2(*(u32*)&A, *(u32*)&B);
        ((uint2*)g_Xl)[i] = make_uint2(*(u32*)&Ar, *(u32*)&Br);
    } else if (i < nx + nw) {
        int j = i - nx;
        ((uint2*)g_Wg16)[j] = f4_to_h4(((const float4*)Wg)[j]);
    } else if (i < nx + 2 * nw) {
        int j = i - nx - nw;
        ((uint2*)g_Wu16)[j] = f4_to_h4(((const float4*)Wu)[j]);
    } else if (i < nx + 3 * nw) {
        int j = i - nx - 2 * nw;
        ((uint2*)g_Wd16)[j] = f4_to_h4(((const float4*)Wd)[j]);
    }
}

// ---- GEMM 1: gate+up. CTA: 128 slots x (32 gate + 32 up), warp tile 32x32 -------
__global__ __launch_bounds__(256, 2) void gateup_mma_kernel() {
    const int e   = blockIdx.z;
    const int cnt = g_cnt[e];
    const int m0  = blockIdx.y * 128;
    if (m0 >= cnt) return;
    const int rows = min(cnt - m0, 128);
    const int base = g_off[e] + m0;
    const int n0   = blockIdx.x * 32;

    extern __shared__ char dsm[];
    const u32 sm0 = smem_u32(dsm);

    const int tid  = threadIdx.x;
    const int lane = tid & 31;
    const int wid  = tid >> 5;
    const int wm   = wid >> 1;          // 0..3 -> 32-row band
    const int wn   = wid & 1;           // 0 = gate 32 B-rows, 1 = up 32 B-rows

    // ---- loader mapping (identical to round 8) ----
    const int q = tid >> 2;             // 0..63
    const int c = tid & 3;
    const int r0 = min(q, rows - 1);
    const int r1 = min(q + 64, rows - 1);
    const size_t xo0 = (size_t)g_perm[base + r0] * HID + c * 8;
    const size_t xo1 = (size_t)g_perm[base + r1] * HID + c * 8;
    const __half* pb;
    if (q < 32) pb = g_Wg16 + ((size_t)e * INTER + n0 + q) * HID + c * 8;
    else        pb = g_Wu16 + ((size_t)e * INTER + n0 + (q - 32)) * HID + c * 8;

    const u32 dA0 = (u32)(OFF_AH + q * PITCH + c * 16);
    const u32 dA1 = dA0 + 64 * PITCH;
    const u32 dL0 = dA0 + (OFF_AL - OFF_AH);
    const u32 dL1 = dA1 + (OFF_AL - OFF_AH);
    const u32 dB  = (u32)(OFF_B + q * PITCH + c * 16);

    // ---- ldmatrix bases: warp tile 32 rows x 32 B-rows ----
    const u32 a_off = (u32)((wm * 32 + (lane & 7) + ((lane >> 3) & 1) * 8) * PITCH
                    + (lane >> 4) * 16);
    const u32 b_off0 = (u32)((wn * 32 + (lane & 7) + (lane >> 4) * 8) * PITCH
                    + ((lane >> 3) & 1) * 16);
    const u32 b_off1 = b_off0 + 16 * PITCH;

    float acc[2][4][4];
    #pragma unroll
    for (int i = 0; i < 2; i++)
        #pragma unroll
        for (int j = 0; j < 4; j++)
            #pragma unroll
            for (int k = 0; k < 4; k++) acc[i][j][k] = 0.0f;

    const int KT = HID / 32;            // 64

    #pragma unroll
    for (int p = 0; p < NSTAGE - 1; p++) {
        const u32 sb = sm0 + (u32)p * STAGE_BYTES;
        const size_t ko = (size_t)p * 32;
        cpa16(sb + dA0, g_Xh + xo0 + ko);
        cpa16(sb + dA1, g_Xh + xo1 + ko);
        cpa16(sb + dL0, g_Xl + xo0 + ko);
        cpa16(sb + dL1, g_Xl + xo1 + ko);
        cpa16(sb + dB,  pb + ko);
        CPA_COMMIT();
    }

    #pragma unroll 1
    for (int kt = 0; kt < KT; kt++) {
        if (kt == KT - 1) CPA_WAIT0(); else CPA_WAIT1();
        __syncthreads();
        if (kt + NSTAGE - 1 < KT) {
            const u32 sb = sm0 + (u32)((kt + NSTAGE - 1) % NSTAGE) * STAGE_BYTES;
            const size_t ko = (size_t)(kt + NSTAGE - 1) * 32;
            cpa16(sb + dA0, g_Xh + xo0 + ko);
            cpa16(sb + dA1, g_Xh + xo1 + ko);
            cpa16(sb + dL0, g_Xl + xo0 + ko);
            cpa16(sb + dL1, g_Xl + xo1 + ko);
            cpa16(sb + dB,  pb + ko);
            CPA_COMMIT();
        }
        const u32 sb = sm0 + (u32)(kt % NSTAGE) * STAGE_BYTES;
        #pragma unroll
        for (int ks = 0; ks < 2; ks++) {
            u32 ah[2][4], al[2][4], bh[2][4];
            #pragma unroll
            for (int mi = 0; mi < 2; mi++) {
                ldsm4(ah[mi], sb + OFF_AH + a_off + (u32)(mi * 16 * PITCH) + (u32)(ks * 32));
                ldsm4(al[mi], sb + OFF_AL + a_off + (u32)(mi * 16 * PITCH) + (u32)(ks * 32));
            }
            ldsm4(bh[0], sb + OFF_B + b_off0 + (u32)(ks * 32));
            ldsm4(bh[1], sb + OFF_B + b_off1 + (u32)(ks * 32));
            #pragma unroll
            for (int mi = 0; mi < 2; mi++) {
                #pragma unroll
                for (int ni = 0; ni < 4; ni++) {
                    const int g = ni >> 1, s = (ni & 1) * 2;
                    mma16816(acc[mi][ni], ah[mi], bh[g][s], bh[g][s + 1]);
                    mma16816(acc[mi][ni], al[mi], bh[g][s], bh[g][s + 1]);
                }
            }
        }
    }
    __syncthreads();

    // ---- epilogue: exchange via smem (128 x 72 f32), silu(g)*u, split hi/lo ----
    // gate warps (wn=0) own S cols 0..31; up warps (wn=1) own S cols 32..63.
    float* S = (float*)dsm;
    #pragma unroll
    for (int mi = 0; mi < 2; mi++) {
        const int rr = wm * 32 + mi * 16 + (lane >> 2);
        #pragma unroll
        for (int ni = 0; ni < 4; ni++) {
            const int cc = wn * 32 + ni * 8 + 2 * (lane & 3);
            *(float2*)(S + (size_t)rr * 72 + cc)       = make_float2(acc[mi][ni][0], acc[mi][ni][1]);
            *(float2*)(S + (size_t)(rr + 8) * 72 + cc) = make_float2(acc[mi][ni][2], acc[mi][ni][3]);
        }
    }
    __syncthreads();
    {
        const int row  = tid >> 1;
        const int half = (tid & 1) * 16;
        if (row < rows) {
            u32 ph[8], pl[8];
            #pragma unroll
            for (int p = 0; p < 8; p++) {
                float g0 = S[(size_t)row * 72 + half + 2 * p];
                float g1 = S[(size_t)row * 72 + half + 2 * p + 1];
                float u0 = S[(size_t)row * 72 + 32 + half + 2 * p];
                float u1 = S[(size_t)row * 72 + 32 + half + 2 * p + 1];
                float h0 = (g0 / (1.0f + expf(-g0))) * u0;
                float h1 = (g1 / (1.0f + expf(-g1))) * u1;
                __half2 A = __floats2half2_rn(h0, h1);
                __half2 B = __floats2half2_rn(h0 - __low2float(A), h1 - __high2float(A));
                ph[p] = *(u32*)&A;
                pl[p] = *(u32*)&B;
            }
            u32* dh = (u32*)(g_Hh + (size_t)(base + row) * INTER + n0 + half);
            u32* dl = (u32*)(g_Hl + (size_t)(base + row) * INTER + n0 + half);
            ((uint4*)dh)[0] = make_uint4(ph[0], ph[1], ph[2], ph[3]);
            ((uint4*)dh)[1] = make_uint4(ph[4], ph[5], ph[6], ph[7]);
            ((uint4*)dl)[0] = make_uint4(pl[0], pl[1], pl[2], pl[3]);
            ((uint4*)dl)[1] = make_uint4(pl[4], pl[5], pl[6], pl[7]);
        }
    }
}

// ---- GEMM 2: down. CTA: 128 slots x 64 hid, warp tile 32x32, K=1024 --------------
__global__ __launch_bounds__(256, 2) void down_mma_kernel() {
    const int e   = blockIdx.z;
    const int cnt = g_cnt[e];
    const int m0  = blockIdx.y * 128;
    if (m0 >= cnt) return;
    const int rows = min(cnt - m0, 128);
    const int base = g_off[e] + m0;
    const int n0   = blockIdx.x * 64;

    extern __shared__ char dsm[];
    const u32 sm0 = smem_u32(dsm);

    const int tid  = threadIdx.x;
    const int lane = tid & 31;
    const int wid  = tid >> 5;
    const int wm   = wid >> 1;          // 0..3
    const int wn   = wid & 1;           // 0..1 -> 32 hid cols each

    const int q = tid >> 2;
    const int c = tid & 3;
    const int r0 = min(q, rows - 1);
    const int r1 = min(q + 64, rows - 1);
    const size_t ho0 = (size_t)(base + r0) * INTER + c * 8;
    const size_t ho1 = (size_t)(base + r1) * INTER + c * 8;
    const __half* pb = g_Wd16 + ((size_t)e * HID + n0 + q) * INTER + c * 8;

    const u32 dA0 = (u32)(OFF_AH + q * PITCH + c * 16);
    const u32 dA1 = dA0 + 64 * PITCH;
    const u32 dL0 = dA0 + (OFF_AL - OFF_AH);
    const u32 dL1 = dA1 + (OFF_AL - OFF_AH);
    const u32 dB  = (u32)(OFF_B + q * PITCH + c * 16);

    const u32 a_off = (u32)((wm * 32 + (lane & 7) + ((lane >> 3) & 1) * 8) * PITCH
                    + (lane >> 4) * 16);
    const u32 b_off0 = (u32)((wn * 32 + (lane & 7) + (lane >> 4) * 8) * PITCH
                    + ((lane >> 3) & 1) * 16);
    const u32 b_off1 = b_off0 + 16 * PITCH;

    float acc[2][4][4];
    #pragma unroll
    for (int i = 0; i < 2; i++)
        #pragma unroll
        for (int j = 0; j < 4; j++)
            #pragma unroll
            for (int k = 0; k < 4; k++) acc[i][j][k] = 0.0f;

    const int KT = INTER / 32;          // 32

    #pragma unroll
    for (int p = 0; p < NSTAGE - 1; p++) {
        const u32 sb = sm0 + (u32)p * STAGE_BYTES;
        const size_t ko = (size_t)p * 32;
        cpa16(sb + dA0, g_Hh + ho0 + ko);
        cpa16(sb + dA1, g_Hh + ho1 + ko);
        cpa16(sb + dL0, g_Hl + ho0 + ko);
        cpa16(sb + dL1, g_Hl + ho1 + ko);
        cpa16(sb + dB,  pb + ko);
        CPA_COMMIT();
    }

    #pragma unroll 1
    for (int kt = 0; kt < KT; kt++) {
        if (kt == KT - 1) CPA_WAIT0(); else CPA_WAIT1();
        __syncthreads();
        if (kt + NSTAGE - 1 < KT) {
            const u32 sb = sm0 + (u32)((kt + NSTAGE - 1) % NSTAGE) * STAGE_BYTES;
            const size_t ko = (size_t)(kt + NSTAGE - 1) * 32;
            cpa16(sb + dA0, g_Hh + ho0 + ko);
            cpa16(sb + dA1, g_Hh + ho1 + ko);
            cpa16(sb + dL0, g_Hl + ho0 + ko);
            cpa16(sb + dL1, g_Hl + ho1 + ko);
            cpa16(sb + dB,  pb + ko);
            CPA_COMMIT();
        }
        const u32 sb = sm0 + (u32)(kt % NSTAGE) * STAGE_BYTES;
        #pragma unroll
        for (int ks = 0; ks < 2; ks++) {
            u32 ah[2][4], al[2][4], bh[2][4];
            #pragma unroll
            for (int mi = 0; mi < 2; mi++) {
                ldsm4(ah[mi], sb + OFF_AH + a_off + (u32)(mi * 16 * PITCH) + (u32)(ks * 32));
                ldsm4(al[mi], sb + OFF_AL + a_off + (u32)(mi * 16 * PITCH) + (u32)(ks * 32));
            }
            ldsm4(bh[0], sb + OFF_B + b_off0 + (u32)(ks * 32));
            ldsm4(bh[1], sb + OFF_B + b_off1 + (u32)(ks * 32));
            #pragma unroll
            for (int mi = 0; mi < 2; mi++) {
                #pragma unroll
                for (int ni = 0; ni < 4; ni++) {
                    const int g = ni >> 1, s = (ni & 1) * 2;
                    mma16816(acc[mi][ni], ah[mi], bh[g][s], bh[g][s + 1]);
                    mma16816(acc[mi][ni], al[mi], bh[g][s], bh[g][s + 1]);
                }
            }
        }
    }

    // ---- epilogue: scale by routing weight, store f32 ----
    #pragma unroll
    for (int mi = 0; mi < 2; mi++) {
        const int r0o = wm * 32 + mi * 16 + (lane >> 2);
        const int r1o = r0o + 8;
        #pragma unroll
        for (int ni = 0; ni < 4; ni++) {
            const int cc = n0 + wn * 32 + ni * 8 + 2 * (lane & 3);
            if (r0o < rows) {
                const float w0 = g_w[base + r0o];
                *(float2*)(g_y + (size_t)(base + r0o) * HID + cc) =
                    make_float2(w0 * acc[mi][ni][0], w0 * acc[mi][ni][1]);
            }
            if (r1o < rows) {
                const float w1 = g_w[base + r1o];
                *(float2*)(g_y + (size_t)(base + r1o) * HID + cc) =
                    make_float2(w1 * acc[mi][ni][2], w1 * acc[mi][ni][3]);
            }
        }
    }
}

// ---- combine: out[t] = y[slot0] + y[slot1] ----------------------------------------
__global__ void combine_kernel(float* __restrict__ out, int T) {
    const int gid = blockIdx.x * blockDim.x + threadIdx.x;
    const int per_tok = HID / 4;
    if (gid >= T * per_tok) return;
    const int t = gid / per_tok;
    const int c = gid - t * per_tok;
    const int s0 = g_slot_of[2 * t];
    const int s1 = g_slot_of[2 * t + 1];
    float4 a = ((const float4*)(g_y + (size_t)s0 * HID))[c];
    float4 b = ((const float4*)(g_y + (size_t)s1 * HID))[c];
    ((float4*)(out + (size_t)t * HID))[c] =
        make_float4(a.x + b.x, a.y + b.y, a.z + b.z, a.w + b.w);
}

// ---- launch -------------------------------------------------------------------------
extern "C" void kernel_launch(void* const* d_in, const int* in_sizes, int n_in,
                              void* d_out, int out_size) {
    if (n_in < 5) return;
    const float* x  = (const float*)d_in[0];
    const float* Wr = (const float*)d_in[1];
    const float* Wg = (const float*)d_in[2];
    const float* Wu = (const float*)d_in[3];
    const float* Wd = (const float*)d_in[4];
    float* out = (float*)d_out;

    int T = in_sizes[0] / HID;
    if (T > MAXT) T = MAXT;

    cudaFuncSetAttribute(gateup_mma_kernel, cudaFuncAttributeMaxDynamicSharedMemorySize, SMEM_DYN);
    cudaFuncSetAttribute(down_mma_kernel,   cudaFuncAttributeMaxDynamicSharedMemorySize, SMEM_DYN);

    const int write_logits = (out_size >= T * HID + T * NEXP);
    float* logits = out + (size_t)T * HID;

    zero_counters_kernel<<<1, 32>>>();
    router_kernel<<<T, 256>>>(x, Wr, logits, write_logits);
    offsets_kernel<<<1, 32>>>();
    scatter_kernel<<<(T + 255) / 256, 256>>>(T);

    const int nx = T * HID / 4;
    const int nw = NEXP * INTER * HID / 4;
    split_all_kernel<<<(nx + 3 * nw + 255) / 256, 256>>>(x, Wg, Wu, Wd, nx, nw);

    gateup_mma_kernel<<<dim3(INTER / 32, MAXSLOTS / 128, NEXP), 256, SMEM_DYN>>>();
    down_mma_kernel<<<dim3(HID / 64, MAXSLOTS / 128, NEXP), 256, SMEM_DYN>>>();

    combine_kernel<<<(T * (HID / 4) + 255) / 256, 256>>>(out, T);
}

// round 10
// speedup vs baseline: 2.5075x; 1.4101x over previous
#include <cuda_runtime.h>
#include <cuda_fp16.h>
#include <cstdint>

// ============================================================================
// BiBoSparseMoeBlock: top-2-of-8 MoE SwiGLU, fp32 in/out.
// Round 10: pure fp16 tensor-core GEMMs (single MMA per k-step; no A split).
// Error budget: ~5e-4 vs 1e-3 gate. Same 256-thr / 2 CTA/SM / 3-stage skeleton.
// ============================================================================

#define HID   2048
#define INTER 1024
#define NEXP  8
#define MAXT  4096
#define MAXSLOTS (2 * MAXT)

typedef unsigned int u32;

// ---- device scratch ---------------------------------------------------------
__device__ int   g_cnt[NEXP];
__device__ int   g_off[NEXP];
__device__ int   g_fill[NEXP];
__device__ int   g_perm[MAXSLOTS];
__device__ float g_w[MAXSLOTS];
__device__ int   g_tidx[MAXT * 2];
__device__ float g_tw[MAXT * 2];
__device__ int   g_slot_of[MAXT * 2];

__device__ __half g_X16[(size_t)MAXT * HID];
__device__ __half g_Wg16[(size_t)NEXP * INTER * HID];
__device__ __half g_Wu16[(size_t)NEXP * INTER * HID];
__device__ __half g_Wd16[(size_t)NEXP * HID * INTER];
__device__ __half g_H16[(size_t)MAXSLOTS * INTER];
__device__ float  g_y[(size_t)MAXSLOTS * HID];

// ---- PTX helpers (baseline sm_80-era only) -------------------------------------
__device__ __forceinline__ u32 smem_u32(const void* p) {
    u32 a;
    asm("{ .reg .u64 t; cvta.to.shared.u64 t, %1; cvt.u32.u64 %0, t; }" : "=r"(a) : "l"(p));
    return a;
}
__device__ __forceinline__ void cpa16(u32 dst, const void* src) {
    asm volatile("cp.async.cg.shared.global [%0], [%1], 16;" :: "r"(dst), "l"(src));
}
#define CPA_COMMIT() asm volatile("cp.async.commit_group;" ::: "memory")
#define CPA_WAIT1()  asm volatile("cp.async.wait_group 1;" ::: "memory")
#define CPA_WAIT0()  asm volatile("cp.async.wait_group 0;" ::: "memory")

__device__ __forceinline__ void ldsm4(u32* r, u32 addr) {
    asm volatile("ldmatrix.sync.aligned.m8n8.x4.shared.b16 {%0,%1,%2,%3}, [%4];"
                 : "=r"(r[0]), "=r"(r[1]), "=r"(r[2]), "=r"(r[3]) : "r"(addr));
}
__device__ __forceinline__ void mma16816(float* c, const u32* a, u32 b0, u32 b1) {
    asm volatile(
        "mma.sync.aligned.m16n8k16.row.col.f32.f16.f16.f32 "
        "{%0,%1,%2,%3}, {%4,%5,%6,%7}, {%8,%9}, {%0,%1,%2,%3};"
        : "+f"(c[0]), "+f"(c[1]), "+f"(c[2]), "+f"(c[3])
        : "r"(a[0]), "r"(a[1]), "r"(a[2]), "r"(a[3]), "r"(b0), "r"(b1));
}

// ---- smem geometry: BK=32 fp16 rows (64B data), pitch 80B ----------------------
#define PITCH 80
#define OFF_A  0              // 128 rows * 80 = 10240
#define OFF_B  10240          // 64 rows * 80 = 5120
#define STAGE_BYTES 15360
#define NSTAGE 3
#define SMEM_DYN (NSTAGE * STAGE_BYTES)   // 46080 -> 2 CTAs/SM easily

// ---- small kernels --------------------------------------------------------------
__global__ void zero_counters_kernel() {
    int i = threadIdx.x;
    if (i < NEXP) { g_cnt[i] = 0; g_fill[i] = 0; }
}

__global__ void router_kernel(const float* __restrict__ x,
                              const float* __restrict__ Wr,
                              float* __restrict__ logits_out, int write_logits) {
    const int t = blockIdx.x;
    const int warp = threadIdx.x >> 5;
    const int lane = threadIdx.x & 31;
    __shared__ float slog[NEXP];
    const float* xr = x + (size_t)t * HID;
    const float* wr = Wr + (size_t)warp * HID;
    float s = 0.0f;
    #pragma unroll 4
    for (int i = lane; i < HID; i += 32) s += xr[i] * wr[i];
    #pragma unroll
    for (int o = 16; o > 0; o >>= 1) s += __shfl_xor_sync(0xffffffffu, s, o);
    if (lane == 0) slog[warp] = s;
    __syncthreads();
    if (write_logits && threadIdx.x < NEXP)
        logits_out[t * NEXP + threadIdx.x] = slog[threadIdx.x];
    if (threadIdx.x == 0) {
        float v0 = -1e30f; int i0 = 0;
        #pragma unroll
        for (int i = 0; i < NEXP; i++) if (slog[i] > v0) { v0 = slog[i]; i0 = i; }
        float v1 = -1e30f; int i1 = 0;
        #pragma unroll
        for (int i = 0; i < NEXP; i++)
            if (i != i0 && slog[i] > v1) { v1 = slog[i]; i1 = i; }
        float ex = expf(v1 - v0);
        float inv = 1.0f / (1.0f + ex);
        g_tidx[2 * t] = i0; g_tidx[2 * t + 1] = i1;
        g_tw[2 * t] = inv;  g_tw[2 * t + 1] = ex * inv;
        atomicAdd(&g_cnt[i0], 1);
        atomicAdd(&g_cnt[i1], 1);
    }
}

__global__ void offsets_kernel() {
    if (threadIdx.x == 0) {
        int o = 0;
        #pragma unroll
        for (int e = 0; e < NEXP; e++) { g_off[e] = o; o += g_cnt[e]; }
    }
}

__global__ void scatter_kernel(int T) {
    int t = blockIdx.x * blockDim.x + threadIdx.x;
    if (t >= T) return;
    #pragma unroll
    for (int j = 0; j < 2; j++) {
        int e = g_tidx[2 * t + j];
        int p = atomicAdd(&g_fill[e], 1);
        int slot = g_off[e] + p;
        g_perm[slot] = t;
        g_w[slot] = g_tw[2 * t + j];
        g_slot_of[2 * t + j] = slot;
    }
}

// ---- conversion pre-pass: fp32 -> fp16 ------------------------------------------
__device__ __forceinline__ uint2 f4_to_h4(const float4 v) {
    __half2 a = __floats2half2_rn(v.x, v.y);
    __half2 b = __floats2half2_rn(v.z, v.w);
    return make_uint2(*(u32*)&a, *(u32*)&b);
}

__global__ void split_all_kernel(const float* __restrict__ x,
                                 const float* __restrict__ Wg,
                                 const float* __restrict__ Wu,
                                 const float* __restrict__ Wd, int nx, int nw) {
    int i = blockIdx.x * blockDim.x + threadIdx.x;
    if (i < nx) {
        ((uint2*)g_X16)[i] = f4_to_h4(((const float4*)x)[i]);
    } else if (i < nx + nw) {
        int j = i - nx;
        ((uint2*)g_Wg16)[j] = f4_to_h4(((const float4*)Wg)[j]);
    } else if (i < nx + 2 * nw) {
        int j = i - nx - nw;
        ((uint2*)g_Wu16)[j] = f4_to_h4(((const float4*)Wu)[j]);
    } else if (i < nx + 3 * nw) {
        int j = i - nx - 2 * nw;
        ((uint2*)g_Wd16)[j] = f4_to_h4(((const float4*)Wd)[j]);
    }
}

// ---- GEMM 1: gate+up. CTA: 128 slots x (32 gate + 32 up), warp tile 32x32 -------
__global__ __launch_bounds__(256, 2) void gateup_mma_kernel() {
    const int e   = blockIdx.z;
    const int cnt = g_cnt[e];
    const int m0  = blockIdx.y * 128;
    if (m0 >= cnt) return;
    const int rows = min(cnt - m0, 128);
    const int base = g_off[e] + m0;
    const int n0   = blockIdx.x * 32;

    extern __shared__ char dsm[];
    const u32 sm0 = smem_u32(dsm);

    const int tid  = threadIdx.x;
    const int lane = tid & 31;
    const int wid  = tid >> 5;
    const int wm   = wid >> 1;          // 0..3 -> 32-row band
    const int wn   = wid & 1;           // 0 = gate cols, 1 = up cols

    // ---- loader: 3 cp.async per thread per stage ----
    const int q = tid >> 2;             // 0..63
    const int c = tid & 3;
    const int r0 = min(q, rows - 1);
    const int r1 = min(q + 64, rows - 1);
    const size_t xo0 = (size_t)g_perm[base + r0] * HID + c * 8;
    const size_t xo1 = (size_t)g_perm[base + r1] * HID + c * 8;
    const __half* pb;
    if (q < 32) pb = g_Wg16 + ((size_t)e * INTER + n0 + q) * HID + c * 8;
    else        pb = g_Wu16 + ((size_t)e * INTER + n0 + (q - 32)) * HID + c * 8;

    const u32 dA0 = (u32)(OFF_A + q * PITCH + c * 16);
    const u32 dA1 = dA0 + 64 * PITCH;
    const u32 dB  = (u32)(OFF_B + q * PITCH + c * 16);

    // ---- ldmatrix bases: warp tile 32 rows x 32 B-rows ----
    const u32 a_off = (u32)((wm * 32 + (lane & 7) + ((lane >> 3) & 1) * 8) * PITCH
                    + (lane >> 4) * 16);
    const u32 b_off0 = (u32)((wn * 32 + (lane & 7) + (lane >> 4) * 8) * PITCH
                    + ((lane >> 3) & 1) * 16);
    const u32 b_off1 = b_off0 + 16 * PITCH;

    float acc[2][4][4];
    #pragma unroll
    for (int i = 0; i < 2; i++)
        #pragma unroll
        for (int j = 0; j < 4; j++)
            #pragma unroll
            for (int k = 0; k < 4; k++) acc[i][j][k] = 0.0f;

    const int KT = HID / 32;            // 64

    #pragma unroll
    for (int p = 0; p < NSTAGE - 1; p++) {
        const u32 sb = sm0 + (u32)p * STAGE_BYTES;
        const size_t ko = (size_t)p * 32;
        cpa16(sb + dA0, g_X16 + xo0 + ko);
        cpa16(sb + dA1, g_X16 + xo1 + ko);
        cpa16(sb + dB,  pb + ko);
        CPA_COMMIT();
    }

    #pragma unroll 1
    for (int kt = 0; kt < KT; kt++) {
        if (kt == KT - 1) CPA_WAIT0(); else CPA_WAIT1();
        __syncthreads();
        if (kt + NSTAGE - 1 < KT) {
            const u32 sb = sm0 + (u32)((kt + NSTAGE - 1) % NSTAGE) * STAGE_BYTES;
            const size_t ko = (size_t)(kt + NSTAGE - 1) * 32;
            cpa16(sb + dA0, g_X16 + xo0 + ko);
            cpa16(sb + dA1, g_X16 + xo1 + ko);
            cpa16(sb + dB,  pb + ko);
            CPA_COMMIT();
        }
        const u32 sb = sm0 + (u32)(kt % NSTAGE) * STAGE_BYTES;
        #pragma unroll
        for (int ks = 0; ks < 2; ks++) {
            u32 ah[2][4], bh[2][4];
            #pragma unroll
            for (int mi = 0; mi < 2; mi++)
                ldsm4(ah[mi], sb + OFF_A + a_off + (u32)(mi * 16 * PITCH) + (u32)(ks * 32));
            ldsm4(bh[0], sb + OFF_B + b_off0 + (u32)(ks * 32));
            ldsm4(bh[1], sb + OFF_B + b_off1 + (u32)(ks * 32));
            #pragma unroll
            for (int mi = 0; mi < 2; mi++) {
                #pragma unroll
                for (int ni = 0; ni < 4; ni++) {
                    const int g = ni >> 1, s = (ni & 1) * 2;
                    mma16816(acc[mi][ni], ah[mi], bh[g][s], bh[g][s + 1]);
                }
            }
        }
    }
    __syncthreads();

    // ---- epilogue: exchange via smem (128 x 72 f32), silu(g)*u, store fp16 ----
    float* S = (float*)dsm;
    #pragma unroll
    for (int mi = 0; mi < 2; mi++) {
        const int rr = wm * 32 + mi * 16 + (lane >> 2);
        #pragma unroll
        for (int ni = 0; ni < 4; ni++) {
            const int cc = wn * 32 + ni * 8 + 2 * (lane & 3);
            *(float2*)(S + (size_t)rr * 72 + cc)       = make_float2(acc[mi][ni][0], acc[mi][ni][1]);
            *(float2*)(S + (size_t)(rr + 8) * 72 + cc) = make_float2(acc[mi][ni][2], acc[mi][ni][3]);
        }
    }
    __syncthreads();
    {
        const int row  = tid >> 1;
        const int half = (tid & 1) * 16;
        if (row < rows) {
            u32 ph[8];
            #pragma unroll
            for (int p = 0; p < 8; p++) {
                float g0 = S[(size_t)row * 72 + half + 2 * p];
                float g1 = S[(size_t)row * 72 + half + 2 * p + 1];
                float u0 = S[(size_t)row * 72 + 32 + half + 2 * p];
                float u1 = S[(size_t)row * 72 + 32 + half + 2 * p + 1];
                float h0 = (g0 / (1.0f + expf(-g0))) * u0;
                float h1 = (g1 / (1.0f + expf(-g1))) * u1;
                __half2 A = __floats2half2_rn(h0, h1);
                ph[p] = *(u32*)&A;
            }
            u32* dh = (u32*)(g_H16 + (size_t)(base + row) * INTER + n0 + half);
            ((uint4*)dh)[0] = make_uint4(ph[0], ph[1], ph[2], ph[3]);
            ((uint4*)dh)[1] = make_uint4(ph[4], ph[5], ph[6], ph[7]);
        }
    }
}

// ---- GEMM 2: down. CTA: 128 slots x 64 hid, warp tile 32x32, K=1024 --------------
__global__ __launch_bounds__(256, 2) void down_mma_kernel() {
    const int e   = blockIdx.z;
    const int cnt = g_cnt[e];
    const int m0  = blockIdx.y * 128;
    if (m0 >= cnt) return;
    const int rows = min(cnt - m0, 128);
    const int base = g_off[e] + m0;
    const int n0   = blockIdx.x * 64;

    extern __shared__ char dsm[];
    const u32 sm0 = smem_u32(dsm);

    const int tid  = threadIdx.x;
    const int lane = tid & 31;
    const int wid  = tid >> 5;
    const int wm   = wid >> 1;
    const int wn   = wid & 1;

    const int q = tid >> 2;
    const int c = tid & 3;
    const int r0 = min(q, rows - 1);
    const int r1 = min(q + 64, rows - 1);
    const size_t ho0 = (size_t)(base + r0) * INTER + c * 8;
    const size_t ho1 = (size_t)(base + r1) * INTER + c * 8;
    const __half* pb = g_Wd16 + ((size_t)e * HID + n0 + q) * INTER + c * 8;

    const u32 dA0 = (u32)(OFF_A + q * PITCH + c * 16);
    const u32 dA1 = dA0 + 64 * PITCH;
    const u32 dB  = (u32)(OFF_B + q * PITCH + c * 16);

    const u32 a_off = (u32)((wm * 32 + (lane & 7) + ((lane >> 3) & 1) * 8) * PITCH
                    + (lane >> 4) * 16);
    const u32 b_off0 = (u32)((wn * 32 + (lane & 7) + (lane >> 4) * 8) * PITCH
                    + ((lane >> 3) & 1) * 16);
    const u32 b_off1 = b_off0 + 16 * PITCH;

    float acc[2][4][4];
    #pragma unroll
    for (int i = 0; i < 2; i++)
        #pragma unroll
        for (int j = 0; j < 4; j++)
            #pragma unroll
            for (int k = 0; k < 4; k++) acc[i][j][k] = 0.0f;

    const int KT = INTER / 32;          // 32

    #pragma unroll
    for (int p = 0; p < NSTAGE - 1; p++) {
        const u32 sb = sm0 + (u32)p * STAGE_BYTES;
        const size_t ko = (size_t)p * 32;
        cpa16(sb + dA0, g_H16 + ho0 + ko);
        cpa16(sb + dA1, g_H16 + ho1 + ko);
        cpa16(sb + dB,  pb + ko);
        CPA_COMMIT();
    }

    #pragma unroll 1
    for (int kt = 0; kt < KT; kt++) {
        if (kt == KT - 1) CPA_WAIT0(); else CPA_WAIT1();
        __syncthreads();
        if (kt + NSTAGE - 1 < KT) {
            const u32 sb = sm0 + (u32)((kt + NSTAGE - 1) % NSTAGE) * STAGE_BYTES;
            const size_t ko = (size_t)(kt + NSTAGE - 1) * 32;
            cpa16(sb + dA0, g_H16 + ho0 + ko);
            cpa16(sb + dA1, g_H16 + ho1 + ko);
            cpa16(sb + dB,  pb + ko);
            CPA_COMMIT();
        }
        const u32 sb = sm0 + (u32)(kt % NSTAGE) * STAGE_BYTES;
        #pragma unroll
        for (int ks = 0; ks < 2; ks++) {
            u32 ah[2][4], bh[2][4];
            #pragma unroll
            for (int mi = 0; mi < 2; mi++)
                ldsm4(ah[mi], sb + OFF_A + a_off + (u32)(mi * 16 * PITCH) + (u32)(ks * 32));
            ldsm4(bh[0], sb + OFF_B + b_off0 + (u32)(ks * 32));
            ldsm4(bh[1], sb + OFF_B + b_off1 + (u32)(ks * 32));
            #pragma unroll
            for (int mi = 0; mi < 2; mi++) {
                #pragma unroll
                for (int ni = 0; ni < 4; ni++) {
                    const int g = ni >> 1, s = (ni & 1) * 2;
                    mma16816(acc[mi][ni], ah[mi], bh[g][s], bh[g][s + 1]);
                }
            }
        }
    }

    // ---- epilogue: scale by routing weight, store f32 ----
    #pragma unroll
    for (int mi = 0; mi < 2; mi++) {
        const int r0o = wm * 32 + mi * 16 + (lane >> 2);
        const int r1o = r0o + 8;
        #pragma unroll
        for (int ni = 0; ni < 4; ni++) {
            const int cc = n0 + wn * 32 + ni * 8 + 2 * (lane & 3);
            if (r0o < rows) {
                const float w0 = g_w[base + r0o];
                *(float2*)(g_y + (size_t)(base + r0o) * HID + cc) =
                    make_float2(w0 * acc[mi][ni][0], w0 * acc[mi][ni][1]);
            }
            if (r1o < rows) {
                const float w1 = g_w[base + r1o];
                *(float2*)(g_y + (size_t)(base + r1o) * HID + cc) =
                    make_float2(w1 * acc[mi][ni][2], w1 * acc[mi][ni][3]);
            }
        }
    }
}

// ---- combine: out[t] = y[slot0] + y[slot1] ----------------------------------------
__global__ void combine_kernel(float* __restrict__ out, int T) {
    const int gid = blockIdx.x * blockDim.x + threadIdx.x;
    const int per_tok = HID / 4;
    if (gid >= T * per_tok) return;
    const int t = gid / per_tok;
    const int c = gid - t * per_tok;
    const int s0 = g_slot_of[2 * t];
    const int s1 = g_slot_of[2 * t + 1];
    float4 a = ((const float4*)(g_y + (size_t)s0 * HID))[c];
    float4 b = ((const float4*)(g_y + (size_t)s1 * HID))[c];
    ((float4*)(out + (size_t)t * HID))[c] =
        make_float4(a.x + b.x, a.y + b.y, a.z + b.z, a.w + b.w);
}

// ---- launch -------------------------------------------------------------------------
extern "C" void kernel_launch(void* const* d_in, const int* in_sizes, int n_in,
                              void* d_out, int out_size) {
    if (n_in < 5) return;
    const float* x  = (const float*)d_in[0];
    const float* Wr = (const float*)d_in[1];
    const float* Wg = (const float*)d_in[2];
    const float* Wu = (const float*)d_in[3];
    const float* Wd = (const float*)d_in[4];
    float* out = (float*)d_out;

    int T = in_sizes[0] / HID;
    if (T > MAXT) T = MAXT;

    cudaFuncSetAttribute(gateup_mma_kernel, cudaFuncAttributeMaxDynamicSharedMemorySize, SMEM_DYN);
    cudaFuncSetAttribute(down_mma_kernel,   cudaFuncAttributeMaxDynamicSharedMemorySize, SMEM_DYN);

    const int write_logits = (out_size >= T * HID + T * NEXP);
    float* logits = out + (size_t)T * HID;

    zero_counters_kernel<<<1, 32>>>();
    router_kernel<<<T, 256>>>(x, Wr, logits, write_logits);
    offsets_kernel<<<1, 32>>>();
    scatter_kernel<<<(T + 255) / 256, 256>>>(T);

    const int nx = T * HID / 4;
    const int nw = NEXP * INTER * HID / 4;
    split_all_kernel<<<(nx + 3 * nw + 255) / 256, 256>>>(x, Wg, Wu, Wd, nx, nw);

    gateup_mma_kernel<<<dim3(INTER / 32, MAXSLOTS / 128, NEXP), 256, SMEM_DYN>>>();
    down_mma_kernel<<<dim3(HID / 64, MAXSLOTS / 128, NEXP), 256, SMEM_DYN>>>();

    combine_kernel<<<(T * (HID / 4) + 255) / 256, 256>>>(out, T);
}